// round 3
// baseline (speedup 1.0000x reference)
#include <cuda_runtime.h>
#include <math.h>

#define Bb 512
#define Tt 32
#define Dd 512
#define Mm 1024
#define Nn (Bb*Tt)

// ---------------- scratch (static device globals; no allocation) ----------------
__device__ float g_adjA[(size_t)Nn * Mm];  // holds sd_a, then adj_a (softmax t=0.5)
__device__ float g_LA  [(size_t)Nn * Mm];  // log(a_pH + 1e-10)
__device__ float g_adjV[(size_t)Nn * Mm];
__device__ float g_LV  [(size_t)Nn * Mm];
__device__ float g_S1  [(size_t)Tt * Bb * Bb];
__device__ float g_S2  [(size_t)Tt * Bb * Bb];
__device__ float g_xa[Nn];
__device__ float g_xv[Nn];
__device__ float g_en[Mm];
__device__ unsigned g_minkey[2];
__device__ double g_acc;

// monotone float<->uint mapping so atomicMin(uint) == min(float)
__device__ __forceinline__ unsigned fenc(float f) {
    unsigned u = __float_as_uint(f);
    return (u & 0x80000000u) ? ~u : (u | 0x80000000u);
}
__device__ __forceinline__ float fdec(unsigned u) {
    return __uint_as_float((u & 0x80000000u) ? (u ^ 0x80000000u) : ~u);
}

__device__ __forceinline__ float warpRedSum(float v) {
    #pragma unroll
    for (int o = 16; o; o >>= 1) v += __shfl_down_sync(0xffffffffu, v, o);
    return v;
}
__device__ __forceinline__ float warpRedMin(float v) {
    #pragma unroll
    for (int o = 16; o; o >>= 1) v = fminf(v, __shfl_down_sync(0xffffffffu, v, o));
    return v;
}

// ---------------- init ----------------
__global__ void k_init() {
    g_minkey[0] = 0xFFFFFFFFu;
    g_minkey[1] = 0xFFFFFFFFu;
    g_acc = 0.0;
}

// ---------------- row squared-norms (rows of length 512) ----------------
__global__ void k_rownorm(const float* __restrict__ src, float* __restrict__ dst) {
    int row = blockIdx.x;
    const float* p = src + (size_t)row * Dd;
    float s = 0.f;
    for (int i = threadIdx.x; i < Dd; i += 128) { float v = p[i]; s += v * v; }
    __shared__ float red[4];
    s = warpRedSum(s);
    int lane = threadIdx.x & 31, wid = threadIdx.x >> 5;
    if (lane == 0) red[wid] = s;
    __syncthreads();
    if (threadIdx.x == 0) dst[row] = red[0] + red[1] + red[2] + red[3];
}

// ---------------- GEMM1: sd = sqrt(max(xn2 + en2 - 2*x.e, 0)), transposed store ----------------
// C tile 128x128, K-tile 16, 256 threads, 8x8 per thread. X:(N,512) E:(M,512), both K-major (NT).
__global__ __launch_bounds__(256) void k_gemm_sd(
    const float* __restrict__ X, const float* __restrict__ E,
    const float* __restrict__ xn2, const float* __restrict__ en2,
    float* __restrict__ outsd)
{
    __shared__ float As[16][128];
    __shared__ float Bs[16][128];
    int tid = threadIdx.x;
    int tx = tid & 15, ty = tid >> 4;
    int n0 = blockIdx.y * 128;
    int m0 = blockIdx.x * 128;

    const float* Ag = X + (size_t)n0 * Dd;
    const float* Bg = E + (size_t)m0 * Dd;

    float acc[8][8];
    #pragma unroll
    for (int i = 0; i < 8; i++)
        #pragma unroll
        for (int j = 0; j < 8; j++) acc[i][j] = 0.f;

    for (int k0 = 0; k0 < Dd; k0 += 16) {
        #pragma unroll
        for (int i = 0; i < 2; i++) {
            int l = tid + i * 256;          // 512 float4 slots per tile
            int r = l >> 2, c4 = l & 3;
            float4 va = *(const float4*)(Ag + (size_t)r * Dd + k0 + c4 * 4);
            As[c4 * 4 + 0][r] = va.x; As[c4 * 4 + 1][r] = va.y;
            As[c4 * 4 + 2][r] = va.z; As[c4 * 4 + 3][r] = va.w;
            float4 vb = *(const float4*)(Bg + (size_t)r * Dd + k0 + c4 * 4);
            Bs[c4 * 4 + 0][r] = vb.x; Bs[c4 * 4 + 1][r] = vb.y;
            Bs[c4 * 4 + 2][r] = vb.z; Bs[c4 * 4 + 3][r] = vb.w;
        }
        __syncthreads();
        #pragma unroll
        for (int k = 0; k < 16; k++) {
            float4 a0 = *(const float4*)&As[k][ty * 8];
            float4 a1 = *(const float4*)&As[k][ty * 8 + 4];
            float4 b0 = *(const float4*)&Bs[k][tx * 8];
            float4 b1 = *(const float4*)&Bs[k][tx * 8 + 4];
            float ra[8] = {a0.x, a0.y, a0.z, a0.w, a1.x, a1.y, a1.z, a1.w};
            float rb[8] = {b0.x, b0.y, b0.z, b0.w, b1.x, b1.y, b1.z, b1.w};
            #pragma unroll
            for (int i = 0; i < 8; i++)
                #pragma unroll
                for (int j = 0; j < 8; j++)
                    acc[i][j] = fmaf(ra[i], rb[j], acc[i][j]);
        }
        __syncthreads();
    }

    #pragma unroll
    for (int i = 0; i < 8; i++) {
        int n = n0 + ty * 8 + i;
        int bI = n >> 5;       // T = 32
        int tI = n & 31;
        size_t rout = (size_t)(tI * Bb + bI) * Mm;   // (T,B,M) layout
        float xn = xn2[n];
        #pragma unroll
        for (int j = 0; j < 8; j++) {
            int m = m0 + tx * 8 + j;
            float sq = xn + en2[m] - 2.f * acc[i][j];
            acc[i][j] = sqrtf(fmaxf(sq, 0.f));
        }
        float4* o = (float4*)(outsd + rout + m0 + tx * 8);
        o[0] = make_float4(acc[i][0], acc[i][1], acc[i][2], acc[i][3]);
        o[1] = make_float4(acc[i][4], acc[i][5], acc[i][6], acc[i][7]);
    }
}

// ---------------- double softmax per row (in-place adj, L out), A and V fused ----------------
__global__ __launch_bounds__(256) void k_softmax()
{
    int row = blockIdx.x;
    float* sd_adj;
    float* Lout;
    if (row < Nn) { sd_adj = g_adjA; Lout = g_LA; }
    else          { sd_adj = g_adjV; Lout = g_LV; row -= Nn; }

    int tid = threadIdx.x;
    size_t base = (size_t)row * Mm;
    float v[4];
    #pragma unroll
    for (int j = 0; j < 4; j++) v[j] = sd_adj[base + tid + j * 256];

    __shared__ float red[8];
    __shared__ float red2[8];
    int lane = tid & 31, wid = tid >> 5;

    // min of sd  ==  -max(-sd)
    float mn = fminf(fminf(v[0], v[1]), fminf(v[2], v[3]));
    mn = warpRedMin(mn);
    if (lane == 0) red[wid] = mn;
    __syncthreads();
    if (tid == 0) {
        float m = red[0];
        #pragma unroll
        for (int w = 1; w < 8; w++) m = fminf(m, red[w]);
        red[0] = m;
    }
    __syncthreads();
    float m = red[0];
    __syncthreads();

    float e1[4], e2[4];
    float s1 = 0.f, s2 = 0.f;
    #pragma unroll
    for (int j = 0; j < 4; j++) {
        float d = v[j] - m;             // >= 0
        e1[j] = expf(-d);
        e2[j] = expf(-2.f * d);
        s1 += e1[j]; s2 += e2[j];
    }
    s1 = warpRedSum(s1); s2 = warpRedSum(s2);
    if (lane == 0) { red[wid] = s1; red2[wid] = s2; }
    __syncthreads();
    if (tid == 0) {
        float a = 0.f, b = 0.f;
        #pragma unroll
        for (int w = 0; w < 8; w++) { a += red[w]; b += red2[w]; }
        red[0] = a; red2[0] = b;
    }
    __syncthreads();
    float inv1 = 1.f / red[0];
    float inv2 = 1.f / red2[0];

    #pragma unroll
    for (int j = 0; j < 4; j++) {
        sd_adj[base + tid + j * 256] = e2[j] * inv2;                 // adj (t=0.5)
        Lout  [base + tid + j * 256] = logf(e1[j] * inv1 + 1e-10f);  // log(pH + 1e-10)
    }
}

// ---------------- GEMM2: Scode[t] = Adj[t] (B,M) . L[t]^T, + global min tracking ----------------
__global__ __launch_bounds__(256) void k_gemm_scode(
    const float* __restrict__ Adj, const float* __restrict__ Lm,
    float* __restrict__ S, int which)
{
    __shared__ float As[16][128];
    __shared__ float Bs[16][128];
    int tid = threadIdx.x;
    int tx = tid & 15, ty = tid >> 4;
    int t  = blockIdx.z;
    int i0 = blockIdx.y * 128;
    int j0 = blockIdx.x * 128;

    const float* Ag = Adj + ((size_t)t * Bb + i0) * Mm;
    const float* Bg = Lm  + ((size_t)t * Bb + j0) * Mm;

    float acc[8][8];
    #pragma unroll
    for (int i = 0; i < 8; i++)
        #pragma unroll
        for (int j = 0; j < 8; j++) acc[i][j] = 0.f;

    for (int k0 = 0; k0 < Mm; k0 += 16) {
        #pragma unroll
        for (int i = 0; i < 2; i++) {
            int l = tid + i * 256;
            int r = l >> 2, c4 = l & 3;
            float4 va = *(const float4*)(Ag + (size_t)r * Mm + k0 + c4 * 4);
            As[c4 * 4 + 0][r] = va.x; As[c4 * 4 + 1][r] = va.y;
            As[c4 * 4 + 2][r] = va.z; As[c4 * 4 + 3][r] = va.w;
            float4 vb = *(const float4*)(Bg + (size_t)r * Mm + k0 + c4 * 4);
            Bs[c4 * 4 + 0][r] = vb.x; Bs[c4 * 4 + 1][r] = vb.y;
            Bs[c4 * 4 + 2][r] = vb.z; Bs[c4 * 4 + 3][r] = vb.w;
        }
        __syncthreads();
        #pragma unroll
        for (int k = 0; k < 16; k++) {
            float4 a0 = *(const float4*)&As[k][ty * 8];
            float4 a1 = *(const float4*)&As[k][ty * 8 + 4];
            float4 b0 = *(const float4*)&Bs[k][tx * 8];
            float4 b1 = *(const float4*)&Bs[k][tx * 8 + 4];
            float ra[8] = {a0.x, a0.y, a0.z, a0.w, a1.x, a1.y, a1.z, a1.w};
            float rb[8] = {b0.x, b0.y, b0.z, b0.w, b1.x, b1.y, b1.z, b1.w};
            #pragma unroll
            for (int i = 0; i < 8; i++)
                #pragma unroll
                for (int j = 0; j < 8; j++)
                    acc[i][j] = fmaf(ra[i], rb[j], acc[i][j]);
        }
        __syncthreads();
    }

    float mn = acc[0][0];
    #pragma unroll
    for (int i = 0; i < 8; i++) {
        size_t off = ((size_t)t * Bb + i0 + ty * 8 + i) * Bb + j0 + tx * 8;
        float4* o = (float4*)(S + off);
        o[0] = make_float4(acc[i][0], acc[i][1], acc[i][2], acc[i][3]);
        o[1] = make_float4(acc[i][4], acc[i][5], acc[i][6], acc[i][7]);
        #pragma unroll
        for (int j = 0; j < 8; j++) mn = fminf(mn, acc[i][j]);
    }

    __shared__ float redm[8];
    mn = warpRedMin(mn);
    int lane = tid & 31, wid = tid >> 5;
    if (lane == 0) redm[wid] = mn;
    __syncthreads();
    if (tid == 0) {
        float m = redm[0];
        #pragma unroll
        for (int w = 1; w < 8; w++) m = fminf(m, redm[w]);
        atomicMin(&g_minkey[which], fenc(m));
    }
}

// ---------------- per-row loss term: log(sum_j exp(S-min)+eps) - (S_diag - min) ----------------
// Fused over both S1 (which=0) and S2 (which=1): grid = 2*T*B blocks.
__global__ __launch_bounds__(256) void k_rowloss()
{
    int r = blockIdx.x;
    int which = 0;
    const float* S = g_S1;
    if (r >= Tt * Bb) { which = 1; S = g_S2; r -= Tt * Bb; }

    float mn = fdec(g_minkey[which]);
    const float* row = S + (size_t)r * Bb;
    int i = r & (Bb - 1);               // B = 512 (power of 2)

    float s = 0.f;
    for (int j = threadIdx.x; j < Bb; j += 256) s += expf(row[j] - mn);

    __shared__ float red[8];
    s = warpRedSum(s);
    int lane = threadIdx.x & 31, wid = threadIdx.x >> 5;
    if (lane == 0) red[wid] = s;
    __syncthreads();
    if (threadIdx.x == 0) {
        float tot = 0.f;
        #pragma unroll
        for (int w = 0; w < 8; w++) tot += red[w];
        double term = log((double)tot + 1e-5) - (double)(row[i] - mn);
        atomicAdd(&g_acc, term);
    }
}

__global__ void k_final(float* out) {
    out[0] = (float)(g_acc * (1.0 / (2.0 * Tt * Bb)));
}

// ---------------- launch ----------------
extern "C" void kernel_launch(void* const* d_in, const int* in_sizes, int n_in,
                              void* d_out, int out_size)
{
    const float* A = (const float*)d_in[0];  // audio_semantic (B,T,D)
    const float* V = (const float*)d_in[1];  // video_semantic
    const float* E = (const float*)d_in[2];  // embedding (M,D)
    float* out = (float*)d_out;

    // One-time symbol-address lookup (deterministic; avoids API calls inside
    // every graph-captured invocation).
    static float *adjA = nullptr, *LA, *adjV, *LV, *S1, *S2, *xa, *xv, *en;
    if (!adjA) {
        cudaGetSymbolAddress((void**)&adjA, g_adjA);
        cudaGetSymbolAddress((void**)&LA,   g_LA);
        cudaGetSymbolAddress((void**)&adjV, g_adjV);
        cudaGetSymbolAddress((void**)&LV,   g_LV);
        cudaGetSymbolAddress((void**)&S1,   g_S1);
        cudaGetSymbolAddress((void**)&S2,   g_S2);
        cudaGetSymbolAddress((void**)&xa,   g_xa);
        cudaGetSymbolAddress((void**)&xv,   g_xv);
        cudaGetSymbolAddress((void**)&en,   g_en);
    }

    k_init<<<1, 1>>>();
    k_rownorm<<<Mm, 128>>>(E, en);
    k_rownorm<<<Nn, 128>>>(A, xa);
    k_rownorm<<<Nn, 128>>>(V, xv);

    dim3 g1(Mm / 128, Nn / 128);
    k_gemm_sd<<<g1, 256>>>(A, E, xa, en, adjA);
    k_gemm_sd<<<g1, 256>>>(V, E, xv, en, adjV);

    k_softmax<<<2 * Nn, 256>>>();

    dim3 g2(Bb / 128, Bb / 128, Tt);
    k_gemm_scode<<<g2, 256>>>(adjA, LV, S1, 0);   // Lcmcm : adj_a . log(v_pH)^T
    k_gemm_scode<<<g2, 256>>>(adjV, LA, S2, 1);   // Lcmcm2: adj_v . log(a_pH)^T

    k_rowloss<<<2 * Tt * Bb, 256>>>();

    k_final<<<1, 1>>>(out);
}

// round 5
// speedup vs baseline: 4.2388x; 4.2388x over previous
#include <cuda_runtime.h>
#include <cuda_bf16.h>
#include <math.h>
#include <stdint.h>

#define Bb 512
#define Tt 32
#define Dd 512
#define Mm 1024
#define Nn (Bb*Tt)

// ---------------- scratch (static device globals; no allocation) ----------------
__device__ float g_sdA[(size_t)Nn * Mm];   // sd_a fp32
__device__ float g_sdV[(size_t)Nn * Mm];
__device__ __nv_bfloat16 g_adjAh[(size_t)Nn * Mm];
__device__ __nv_bfloat16 g_LAh [(size_t)Nn * Mm];
__device__ __nv_bfloat16 g_adjVh[(size_t)Nn * Mm];
__device__ __nv_bfloat16 g_LVh [(size_t)Nn * Mm];
__device__ __nv_bfloat16 g_Ah[(size_t)Nn * Dd];
__device__ __nv_bfloat16 g_Vh[(size_t)Nn * Dd];
__device__ __nv_bfloat16 g_Eh[(size_t)Mm * Dd];
__device__ float g_S1[(size_t)Tt * Bb * Bb];
__device__ float g_S2[(size_t)Tt * Bb * Bb];
__device__ float g_xa[Nn];
__device__ float g_xv[Nn];
__device__ float g_en[Mm];
__device__ unsigned g_minkey[2];
__device__ double g_acc;

// ---------------- helpers ----------------
__device__ __forceinline__ unsigned fenc(float f) {
    unsigned u = __float_as_uint(f);
    return (u & 0x80000000u) ? ~u : (u | 0x80000000u);
}
__device__ __forceinline__ float fdec(unsigned u) {
    return __uint_as_float((u & 0x80000000u) ? (u ^ 0x80000000u) : ~u);
}
__device__ __forceinline__ float warpRedSum(float v) {
    #pragma unroll
    for (int o = 16; o; o >>= 1) v += __shfl_down_sync(0xffffffffu, v, o);
    return v;
}
__device__ __forceinline__ float warpRedMin(float v) {
    #pragma unroll
    for (int o = 16; o; o >>= 1) v = fminf(v, __shfl_down_sync(0xffffffffu, v, o));
    return v;
}

__device__ __forceinline__ void cp16(uint32_t s, const void* g) {
    asm volatile("cp.async.cg.shared.global [%0], [%1], 16;"
                 :: "r"(s), "l"(__cvta_generic_to_global(g)) : "memory");
}
#define CP_COMMIT() asm volatile("cp.async.commit_group;" ::: "memory")
#define CP_WAIT1()  asm volatile("cp.async.wait_group 1;" ::: "memory")
#define CP_WAIT0()  asm volatile("cp.async.wait_group 0;" ::: "memory")

#define LDSM4(r0, r1, r2, r3, a) \
    asm volatile("ldmatrix.sync.aligned.m8n8.x4.shared.b16 {%0,%1,%2,%3}, [%4];" \
                 : "=r"(r0), "=r"(r1), "=r"(r2), "=r"(r3) : "r"(a) : "memory")

#define MMA16816(c, a, b) \
    asm volatile("mma.sync.aligned.m16n8k16.row.col.f32.bf16.bf16.f32 " \
                 "{%0,%1,%2,%3}, {%4,%5,%6,%7}, {%8,%9}, {%0,%1,%2,%3};" \
                 : "+f"((c)[0]), "+f"((c)[1]), "+f"((c)[2]), "+f"((c)[3]) \
                 : "r"((a)[0]), "r"((a)[1]), "r"((a)[2]), "r"((a)[3]), \
                   "r"((b)[0]), "r"((b)[1]))

// Smem tile: 128 rows x 32 bf16, padded to 40 bf16 (80B) per row. Per buffer 10240B.
#define ROWB 80
#define TILEB (128 * ROWB)      // 10240 bytes per matrix per buffer

// issue one k-tile (A and B, 128x32 bf16 each) via cp.async
__device__ __forceinline__ void issue_tile(
    uint32_t sA, uint32_t sB,
    const __nv_bfloat16* __restrict__ Ag, const __nv_bfloat16* __restrict__ Bg,
    int ld, int k0, int tid)
{
    #pragma unroll
    for (int i = 0; i < 2; i++) {
        int chunk = tid + i * 256;          // 512 chunks of 16B per matrix
        int row = chunk >> 2, c4 = chunk & 3;
        uint32_t so = (uint32_t)row * ROWB + c4 * 16;
        cp16(sA + so, Ag + (size_t)row * ld + k0 + c4 * 8);
        cp16(sB + so, Bg + (size_t)row * ld + k0 + c4 * 8);
    }
    CP_COMMIT();
}

// compute one k-tile (K=32): warp (wm in 0..1 -> 64 rows, wn in 0..3 -> 32 cols)
__device__ __forceinline__ void compute_tile(
    uint32_t sA, uint32_t sB, int wm, int wn, int lane, float acc[4][4][4])
{
    #pragma unroll
    for (int s = 0; s < 2; s++) {           // two k16 steps
        uint32_t a[4][4];
        #pragma unroll
        for (int i = 0; i < 4; i++) {
            uint32_t addr = sA + (uint32_t)(wm * 64 + i * 16 + (lane & 15)) * ROWB
                          + s * 32 + (lane >> 4) * 16;
            LDSM4(a[i][0], a[i][1], a[i][2], a[i][3], addr);
        }
        uint32_t b[4][2];
        #pragma unroll
        for (int jj = 0; jj < 2; jj++) {
            uint32_t addr = sB + (uint32_t)(wn * 32 + jj * 16 + ((lane >> 4) * 8 + (lane & 7))) * ROWB
                          + ((lane >> 3) & 1) * 16 + s * 32;
            uint32_t r0, r1, r2, r3;
            LDSM4(r0, r1, r2, r3, addr);
            b[jj * 2][0] = r0; b[jj * 2][1] = r1;
            b[jj * 2 + 1][0] = r2; b[jj * 2 + 1][1] = r3;
        }
        #pragma unroll
        for (int i = 0; i < 4; i++)
            #pragma unroll
            for (int j = 0; j < 4; j++)
                MMA16816(acc[i][j], a[i], b[j]);
    }
}

// full double-buffered mainloop
__device__ __forceinline__ void hmma_mainloop(
    uint32_t sb, const __nv_bfloat16* __restrict__ Ag, const __nv_bfloat16* __restrict__ Bg,
    int ld, int NT, int tid, int wm, int wn, int lane, float acc[4][4][4])
{
    uint32_t sA0 = sb, sA1 = sb + TILEB;
    uint32_t sB0 = sb + 2 * TILEB, sB1 = sb + 3 * TILEB;

    issue_tile(sA0, sB0, Ag, Bg, ld, 0, tid);
    for (int kt = 0; kt < NT; kt++) {
        uint32_t sA = (kt & 1) ? sA1 : sA0;
        uint32_t sB = (kt & 1) ? sB1 : sB0;
        if (kt + 1 < NT) {
            issue_tile((kt & 1) ? sA0 : sA1, (kt & 1) ? sB0 : sB1, Ag, Bg, ld, (kt + 1) * 32, tid);
            CP_WAIT1();
        } else {
            CP_WAIT0();
        }
        __syncthreads();
        compute_tile(sA, sB, wm, wn, lane, acc);
        __syncthreads();
    }
}

// ---------------- init ----------------
__global__ void k_init() {
    g_minkey[0] = 0xFFFFFFFFu;
    g_minkey[1] = 0xFFFFFFFFu;
    g_acc = 0.0;
}

// ---------------- fused fp32->bf16 convert + row squared-norm ----------------
__global__ __launch_bounds__(128) void k_cvt(
    const float* __restrict__ A, const float* __restrict__ V, const float* __restrict__ E)
{
    int row = blockIdx.x;
    const float* src; __nv_bfloat16* dst; float* nrm; int r;
    if (row < Nn)          { src = A; dst = g_Ah; nrm = g_xa; r = row; }
    else if (row < 2 * Nn) { src = V; dst = g_Vh; nrm = g_xv; r = row - Nn; }
    else                   { src = E; dst = g_Eh; nrm = g_en; r = row - 2 * Nn; }

    int t = threadIdx.x;
    float4 v = *(const float4*)(src + (size_t)r * Dd + t * 4);
    float s = v.x * v.x + v.y * v.y + v.z * v.z + v.w * v.w;

    __nv_bfloat162 lo = __floats2bfloat162_rn(v.x, v.y);
    __nv_bfloat162 hi = __floats2bfloat162_rn(v.z, v.w);
    uint2 pk;
    pk.x = *(unsigned*)&lo;
    pk.y = *(unsigned*)&hi;
    *(uint2*)(dst + (size_t)r * Dd + t * 4) = pk;

    __shared__ float red[4];
    s = warpRedSum(s);
    int lane = t & 31, wid = t >> 5;
    if (lane == 0) red[wid] = s;
    __syncthreads();
    if (t == 0) nrm[r] = red[0] + red[1] + red[2] + red[3];
}

// ---------------- GEMM1 (HMMA): sd = sqrt(max(xn2+en2-2*x.e,0)) -> (T,B,M) ----------------
__global__ __launch_bounds__(256) void k_hmma_sd(int which)
{
    __shared__ __align__(16) char sm[4 * TILEB];
    uint32_t sb = (uint32_t)__cvta_generic_to_shared(sm);
    int tid = threadIdx.x, wid = tid >> 5, lane = tid & 31;
    int wm = wid & 1, wn = wid >> 1;
    int m0 = blockIdx.x * 128, n0 = blockIdx.y * 128;

    const __nv_bfloat16* X = which ? g_Vh : g_Ah;
    const float* xn2 = which ? g_xv : g_xa;
    float* outsd = which ? g_sdV : g_sdA;

    float acc[4][4][4];
    #pragma unroll
    for (int i = 0; i < 4; i++)
        #pragma unroll
        for (int j = 0; j < 4; j++)
            #pragma unroll
            for (int c = 0; c < 4; c++) acc[i][j][c] = 0.f;

    hmma_mainloop(sb, X + (size_t)n0 * Dd, g_Eh + (size_t)m0 * Dd, Dd, Dd / 32,
                  tid, wm, wn, lane, acc);

    int g = lane >> 2, tg = lane & 3;
    #pragma unroll
    for (int i = 0; i < 4; i++) {
        int n_lo = n0 + wm * 64 + i * 16 + g;
        int n_hi = n_lo + 8;
        float xlo = xn2[n_lo], xhi = xn2[n_hi];
        float* rl = outsd + ((size_t)((n_lo & 31) * Bb + (n_lo >> 5))) * Mm;
        float* rh = outsd + ((size_t)((n_hi & 31) * Bb + (n_hi >> 5))) * Mm;
        #pragma unroll
        for (int j = 0; j < 4; j++) {
            int m = m0 + wn * 32 + j * 8 + tg * 2;
            float e0 = g_en[m], e1 = g_en[m + 1];
            float2 lo, hi;
            lo.x = sqrtf(fmaxf(fmaf(-2.f, acc[i][j][0], xlo + e0), 0.f));
            lo.y = sqrtf(fmaxf(fmaf(-2.f, acc[i][j][1], xlo + e1), 0.f));
            hi.x = sqrtf(fmaxf(fmaf(-2.f, acc[i][j][2], xhi + e0), 0.f));
            hi.y = sqrtf(fmaxf(fmaf(-2.f, acc[i][j][3], xhi + e1), 0.f));
            *(float2*)(rl + m) = lo;
            *(float2*)(rh + m) = hi;
        }
    }
}

// ---------------- double softmax per row -> bf16 adj + bf16 log(pH) ----------------
__global__ __launch_bounds__(256) void k_softmax()
{
    int row = blockIdx.x;
    const float* sd; __nv_bfloat16 *adjh, *Lh;
    if (row < Nn) { sd = g_sdA; adjh = g_adjAh; Lh = g_LAh; }
    else          { sd = g_sdV; adjh = g_adjVh; Lh = g_LVh; row -= Nn; }

    int tid = threadIdx.x;
    size_t bidx = (size_t)row * Mm;
    float4 v4 = *(const float4*)(sd + bidx + tid * 4);
    float v[4] = {v4.x, v4.y, v4.z, v4.w};

    __shared__ float red[8];
    __shared__ float red2[8];
    int lane = tid & 31, wid = tid >> 5;

    float mn = fminf(fminf(v[0], v[1]), fminf(v[2], v[3]));
    mn = warpRedMin(mn);
    if (lane == 0) red[wid] = mn;
    __syncthreads();
    if (tid == 0) {
        float m = red[0];
        #pragma unroll
        for (int w = 1; w < 8; w++) m = fminf(m, red[w]);
        red[0] = m;
    }
    __syncthreads();
    float m = red[0];
    __syncthreads();

    float e1[4], e2[4], s1 = 0.f, s2 = 0.f;
    #pragma unroll
    for (int j = 0; j < 4; j++) {
        float d = v[j] - m;
        e1[j] = expf(-d);
        e2[j] = expf(-2.f * d);
        s1 += e1[j]; s2 += e2[j];
    }
    s1 = warpRedSum(s1); s2 = warpRedSum(s2);
    if (lane == 0) { red[wid] = s1; red2[wid] = s2; }
    __syncthreads();
    if (tid == 0) {
        float a = 0.f, b = 0.f;
        #pragma unroll
        for (int w = 0; w < 8; w++) { a += red[w]; b += red2[w]; }
        red[0] = a; red2[0] = b;
    }
    __syncthreads();
    float inv1 = 1.f / red[0];
    float inv2 = 1.f / red2[0];

    __nv_bfloat162 a01 = __floats2bfloat162_rn(e2[0] * inv2, e2[1] * inv2);
    __nv_bfloat162 a23 = __floats2bfloat162_rn(e2[2] * inv2, e2[3] * inv2);
    __nv_bfloat162 l01 = __floats2bfloat162_rn(logf(e1[0] * inv1 + 1e-10f), logf(e1[1] * inv1 + 1e-10f));
    __nv_bfloat162 l23 = __floats2bfloat162_rn(logf(e1[2] * inv1 + 1e-10f), logf(e1[3] * inv1 + 1e-10f));
    *(__nv_bfloat162*)(adjh + bidx + tid * 4)     = a01;
    *(__nv_bfloat162*)(adjh + bidx + tid * 4 + 2) = a23;
    *(__nv_bfloat162*)(Lh + bidx + tid * 4)       = l01;
    *(__nv_bfloat162*)(Lh + bidx + tid * 4 + 2)   = l23;
}

// ---------------- GEMM2 (HMMA): Scode[t] = Adj[t] . L[t]^T + min tracking ----------------
__global__ __launch_bounds__(256) void k_hmma_scode(int which)
{
    __shared__ __align__(16) char sm[4 * TILEB];
    __shared__ float redm[8];
    uint32_t sb = (uint32_t)__cvta_generic_to_shared(sm);
    int tid = threadIdx.x, wid = tid >> 5, lane = tid & 31;
    int wm = wid & 1, wn = wid >> 1;
    int t = blockIdx.z;
    int i0 = blockIdx.y * 128, j0 = blockIdx.x * 128;

    const __nv_bfloat16* Adj = which ? g_adjVh : g_adjAh;
    const __nv_bfloat16* Lm  = which ? g_LAh   : g_LVh;
    float* S = which ? g_S2 : g_S1;

    float acc[4][4][4];
    #pragma unroll
    for (int i = 0; i < 4; i++)
        #pragma unroll
        for (int j = 0; j < 4; j++)
            #pragma unroll
            for (int c = 0; c < 4; c++) acc[i][j][c] = 0.f;

    hmma_mainloop(sb,
                  Adj + ((size_t)t * Bb + i0) * Mm,
                  Lm  + ((size_t)t * Bb + j0) * Mm,
                  Mm, Mm / 32, tid, wm, wn, lane, acc);

    int g = lane >> 2, tg = lane & 3;
    float mn = 3.402823466e38f;
    #pragma unroll
    for (int i = 0; i < 4; i++) {
        int r_lo = i0 + wm * 64 + i * 16 + g;
        float* rl = S + ((size_t)t * Bb + r_lo) * Bb;
        float* rh = rl + (size_t)8 * Bb;
        #pragma unroll
        for (int j = 0; j < 4; j++) {
            int c = j0 + wn * 32 + j * 8 + tg * 2;
            float2 lo = make_float2(acc[i][j][0], acc[i][j][1]);
            float2 hi = make_float2(acc[i][j][2], acc[i][j][3]);
            mn = fminf(mn, fminf(fminf(lo.x, lo.y), fminf(hi.x, hi.y)));
            *(float2*)(rl + c) = lo;
            *(float2*)(rh + c) = hi;
        }
    }

    mn = warpRedMin(mn);
    if (lane == 0) redm[wid] = mn;
    __syncthreads();
    if (tid == 0) {
        float m = redm[0];
        #pragma unroll
        for (int w = 1; w < 8; w++) m = fminf(m, redm[w]);
        atomicMin(&g_minkey[which], fenc(m));
    }
}

// ---------------- per-row loss term ----------------
__global__ __launch_bounds__(256) void k_rowloss()
{
    int r = blockIdx.x;
    int which = 0;
    const float* S = g_S1;
    if (r >= Tt * Bb) { which = 1; S = g_S2; r -= Tt * Bb; }

    float mn = fdec(g_minkey[which]);
    const float* row = S + (size_t)r * Bb;
    int i = r & (Bb - 1);

    float s = 0.f;
    for (int j = threadIdx.x; j < Bb; j += 256) s += expf(row[j] - mn);

    __shared__ float red[8];
    s = warpRedSum(s);
    int lane = threadIdx.x & 31, wid = threadIdx.x >> 5;
    if (lane == 0) red[wid] = s;
    __syncthreads();
    if (threadIdx.x == 0) {
        float tot = 0.f;
        #pragma unroll
        for (int w = 0; w < 8; w++) tot += red[w];
        double term = log((double)tot + 1e-5) - (double)(row[i] - mn);
        atomicAdd(&g_acc, term);
    }
}

__global__ void k_final(float* out) {
    out[0] = (float)(g_acc * (1.0 / (2.0 * Tt * Bb)));
}

// ---------------- launch ----------------
extern "C" void kernel_launch(void* const* d_in, const int* in_sizes, int n_in,
                              void* d_out, int out_size)
{
    const float* A = (const float*)d_in[0];
    const float* V = (const float*)d_in[1];
    const float* E = (const float*)d_in[2];
    float* out = (float*)d_out;

    k_init<<<1, 1>>>();
    k_cvt<<<2 * Nn + Mm, 128>>>(A, V, E);

    dim3 g1(Mm / 128, Nn / 128);
    k_hmma_sd<<<g1, 256>>>(0);
    k_hmma_sd<<<g1, 256>>>(1);

    k_softmax<<<2 * Nn, 256>>>();

    dim3 g2(Bb / 128, Bb / 128, Tt);
    k_hmma_scode<<<g2, 256>>>(0);   // adj_a . log(v_pH)^T
    k_hmma_scode<<<g2, 256>>>(1);   // adj_v . log(a_pH)^T

    k_rowloss<<<2 * Tt * Bb, 256>>>();
    k_final<<<1, 1>>>(out);
}

// round 8
// speedup vs baseline: 4.5226x; 1.0670x over previous
#include <cuda_runtime.h>
#include <cuda_bf16.h>
#include <math.h>
#include <stdint.h>

#define Bb 512
#define Tt 32
#define Dd 512
#define Mm 1024
#define Nn (Bb*Tt)

// ---------------- scratch (static device globals; no allocation) ----------------
__device__ float g_sdA[(size_t)Nn * Mm];
__device__ float g_sdV[(size_t)Nn * Mm];
__device__ __nv_bfloat16 g_adjAh[(size_t)Nn * Mm];
__device__ __nv_bfloat16 g_LAh [(size_t)Nn * Mm];
__device__ __nv_bfloat16 g_adjVh[(size_t)Nn * Mm];
__device__ __nv_bfloat16 g_LVh [(size_t)Nn * Mm];
__device__ __nv_bfloat16 g_Ah[(size_t)Nn * Dd];
__device__ __nv_bfloat16 g_Vh[(size_t)Nn * Dd];
__device__ __nv_bfloat16 g_Eh[(size_t)Mm * Dd];
__device__ float g_xa[Nn];
__device__ float g_xv[Nn];
__device__ float g_en[Mm];
__device__ float g_pmax[2 * Tt * Bb * 2];   // [which][t][row][jhalf]
__device__ float g_psum[2 * Tt * Bb * 2];
__device__ float g_diag[2 * Tt * Bb];
__device__ unsigned g_minkey[2];
__device__ double g_acc;

// ---------------- helpers ----------------
__device__ __forceinline__ unsigned fenc(float f) {
    unsigned u = __float_as_uint(f);
    return (u & 0x80000000u) ? ~u : (u | 0x80000000u);
}
__device__ __forceinline__ float fdec(unsigned u) {
    return __uint_as_float((u & 0x80000000u) ? (u ^ 0x80000000u) : ~u);
}
__device__ __forceinline__ float warpRedSum(float v) {
    #pragma unroll
    for (int o = 16; o; o >>= 1) v += __shfl_down_sync(0xffffffffu, v, o);
    return v;
}
__device__ __forceinline__ float warpRedMin(float v) {
    #pragma unroll
    for (int o = 16; o; o >>= 1) v = fminf(v, __shfl_down_sync(0xffffffffu, v, o));
    return v;
}

__device__ __forceinline__ void cp16(uint32_t s, const void* g) {
    asm volatile("cp.async.cg.shared.global [%0], [%1], 16;"
                 :: "r"(s), "l"(__cvta_generic_to_global(g)) : "memory");
}
#define CP_COMMIT() asm volatile("cp.async.commit_group;" ::: "memory")
#define CP_WAIT1()  asm volatile("cp.async.wait_group 1;" ::: "memory")
#define CP_WAIT0()  asm volatile("cp.async.wait_group 0;" ::: "memory")

#define LDSM4(r0, r1, r2, r3, a) \
    asm volatile("ldmatrix.sync.aligned.m8n8.x4.shared.b16 {%0,%1,%2,%3}, [%4];" \
                 : "=r"(r0), "=r"(r1), "=r"(r2), "=r"(r3) : "r"(a) : "memory")

#define MMA16816(c, a, b) \
    asm volatile("mma.sync.aligned.m16n8k16.row.col.f32.bf16.bf16.f32 " \
                 "{%0,%1,%2,%3}, {%4,%5,%6,%7}, {%8,%9}, {%0,%1,%2,%3};" \
                 : "+f"((c)[0]), "+f"((c)[1]), "+f"((c)[2]), "+f"((c)[3]) \
                 : "r"((a)[0]), "r"((a)[1]), "r"((a)[2]), "r"((a)[3]), \
                   "r"((b)[0]), "r"((b)[1]))

// smem: per stage A(128x32 bf16, 80B rows) + B(256x32 bf16, 80B rows)
#define ROWB 80
#define A_B  (128 * ROWB)           // 10240
#define STAGE ((128 + 256) * ROWB)  // 30720
#define NSTG 3
#define DSM (NSTG * STAGE)          // 92160

// issue one k-tile: A 128x32, B 256x32 bf16 via cp.async (6 x 16B per thread)
__device__ __forceinline__ void issue_tile(
    uint32_t st, const __nv_bfloat16* __restrict__ Ag, const __nv_bfloat16* __restrict__ Bg,
    int ld, int k0, int tid)
{
    #pragma unroll
    for (int i = 0; i < 2; i++) {                  // A: 512 chunks
        int ch = tid + i * 256;
        int row = ch >> 2, c4 = ch & 3;
        cp16(st + (uint32_t)row * ROWB + c4 * 16, Ag + (size_t)row * ld + k0 + c4 * 8);
    }
    #pragma unroll
    for (int i = 0; i < 4; i++) {                  // B: 1024 chunks
        int ch = tid + i * 256;
        int row = ch >> 2, c4 = ch & 3;
        cp16(st + A_B + (uint32_t)row * ROWB + c4 * 16, Bg + (size_t)row * ld + k0 + c4 * 8);
    }
    CP_COMMIT();
}

// compute one k32 tile: warp tile 64x64 (wm 0..1, wn 0..3)
__device__ __forceinline__ void compute_tile(
    uint32_t st, int wm, int wn, int lane, float acc[4][8][4])
{
    uint32_t sA = st, sB = st + A_B;
    #pragma unroll
    for (int s = 0; s < 2; s++) {
        uint32_t a[4][4];
        #pragma unroll
        for (int i = 0; i < 4; i++) {
            uint32_t addr = sA + (uint32_t)(wm * 64 + i * 16 + (lane & 15)) * ROWB
                          + s * 32 + (lane >> 4) * 16;
            LDSM4(a[i][0], a[i][1], a[i][2], a[i][3], addr);
        }
        uint32_t b[8][2];
        #pragma unroll
        for (int jj = 0; jj < 4; jj++) {
            uint32_t addr = sB + (uint32_t)(wn * 64 + jj * 16 + ((lane >> 4) * 8 + (lane & 7))) * ROWB
                          + ((lane >> 3) & 1) * 16 + s * 32;
            uint32_t r0, r1, r2, r3;
            LDSM4(r0, r1, r2, r3, addr);
            b[jj * 2][0] = r0;     b[jj * 2][1] = r1;
            b[jj * 2 + 1][0] = r2; b[jj * 2 + 1][1] = r3;
        }
        #pragma unroll
        for (int i = 0; i < 4; i++)
            #pragma unroll
            for (int j = 0; j < 8; j++)
                MMA16816(acc[i][j], a[i], b[j]);
    }
}

// 3-stage pipelined mainloop, one __syncthreads per k-tile
__device__ __forceinline__ void hmma_mainloop(
    uint32_t sb, const __nv_bfloat16* __restrict__ Ag, const __nv_bfloat16* __restrict__ Bg,
    int ld, int NT, int tid, int wm, int wn, int lane, float acc[4][8][4])
{
    issue_tile(sb, Ag, Bg, ld, 0, tid);
    issue_tile(sb + STAGE, Ag, Bg, ld, 32, tid);
    for (int kt = 0; kt < NT; kt++) {
        if (kt + 1 < NT) CP_WAIT1(); else CP_WAIT0();
        __syncthreads();
        if (kt + 2 < NT)
            issue_tile(sb + ((kt + 2) % 3) * STAGE, Ag, Bg, ld, (kt + 2) * 32, tid);
        compute_tile(sb + (kt % 3) * STAGE, wm, wn, lane, acc);
    }
}

// ---------------- init ----------------
__global__ void k_init() {
    g_minkey[0] = 0xFFFFFFFFu;
    g_minkey[1] = 0xFFFFFFFFu;
    g_acc = 0.0;
}

// ---------------- fused fp32->bf16 convert + row squared-norm ----------------
__global__ __launch_bounds__(128) void k_cvt(
    const float* __restrict__ A, const float* __restrict__ V, const float* __restrict__ E)
{
    int row = blockIdx.x;
    const float* src; __nv_bfloat16* dst; float* nrm; int r;
    if (row < Nn)          { src = A; dst = g_Ah; nrm = g_xa; r = row; }
    else if (row < 2 * Nn) { src = V; dst = g_Vh; nrm = g_xv; r = row - Nn; }
    else                   { src = E; dst = g_Eh; nrm = g_en; r = row - 2 * Nn; }

    int t = threadIdx.x;
    float4 v = *(const float4*)(src + (size_t)r * Dd + t * 4);
    float s = v.x * v.x + v.y * v.y + v.z * v.z + v.w * v.w;

    __nv_bfloat162 lo = __floats2bfloat162_rn(v.x, v.y);
    __nv_bfloat162 hi = __floats2bfloat162_rn(v.z, v.w);
    uint2 pk;
    pk.x = *(unsigned*)&lo;
    pk.y = *(unsigned*)&hi;
    *(uint2*)(dst + (size_t)r * Dd + t * 4) = pk;

    __shared__ float red[4];
    s = warpRedSum(s);
    int lane = t & 31, wid = t >> 5;
    if (lane == 0) red[wid] = s;
    __syncthreads();
    if (t == 0) nrm[r] = red[0] + red[1] + red[2] + red[3];
}

// ---------------- GEMM1 (HMMA 128x256): sd -> (T,B,M) ----------------
__global__ __launch_bounds__(256) void k_hmma_sd(int which)
{
    extern __shared__ __align__(16) char sm[];
    uint32_t sb = (uint32_t)__cvta_generic_to_shared(sm);
    int tid = threadIdx.x, wid = tid >> 5, lane = tid & 31;
    int wm = wid & 1, wn = wid >> 1;
    int m0 = blockIdx.x * 256, n0 = blockIdx.y * 128;

    const __nv_bfloat16* X = which ? g_Vh : g_Ah;
    const float* xn2 = which ? g_xv : g_xa;
    float* outsd = which ? g_sdV : g_sdA;

    float acc[4][8][4];
    #pragma unroll
    for (int i = 0; i < 4; i++)
        #pragma unroll
        for (int j = 0; j < 8; j++)
            #pragma unroll
            for (int c = 0; c < 4; c++) acc[i][j][c] = 0.f;

    hmma_mainloop(sb, X + (size_t)n0 * Dd, g_Eh + (size_t)m0 * Dd, Dd, Dd / 32,
                  tid, wm, wn, lane, acc);

    int g = lane >> 2, tg = lane & 3;
    #pragma unroll
    for (int i = 0; i < 4; i++) {
        int n_lo = n0 + wm * 64 + i * 16 + g;
        int n_hi = n_lo + 8;
        float xlo = xn2[n_lo], xhi = xn2[n_hi];
        float* rl = outsd + ((size_t)((n_lo & 31) * Bb + (n_lo >> 5))) * Mm;
        float* rh = outsd + ((size_t)((n_hi & 31) * Bb + (n_hi >> 5))) * Mm;
        #pragma unroll
        for (int j = 0; j < 8; j++) {
            int m = m0 + wn * 64 + j * 8 + tg * 2;
            float e0 = g_en[m], e1 = g_en[m + 1];
            float2 lo, hi;
            lo.x = sqrtf(fmaxf(fmaf(-2.f, acc[i][j][0], xlo + e0), 0.f));
            lo.y = sqrtf(fmaxf(fmaf(-2.f, acc[i][j][1], xlo + e1), 0.f));
            hi.x = sqrtf(fmaxf(fmaf(-2.f, acc[i][j][2], xhi + e0), 0.f));
            hi.y = sqrtf(fmaxf(fmaf(-2.f, acc[i][j][3], xhi + e1), 0.f));
            *(float2*)(rl + m) = lo;
            *(float2*)(rh + m) = hi;
        }
    }
}

// ---------------- double softmax per row -> bf16 adj + bf16 log(pH) ----------------
__global__ __launch_bounds__(256) void k_softmax()
{
    int row = blockIdx.x;
    const float* sd; __nv_bfloat16 *adjh, *Lh;
    if (row < Nn) { sd = g_sdA; adjh = g_adjAh; Lh = g_LAh; }
    else          { sd = g_sdV; adjh = g_adjVh; Lh = g_LVh; row -= Nn; }

    int tid = threadIdx.x;
    size_t bidx = (size_t)row * Mm;
    float4 v4 = *(const float4*)(sd + bidx + tid * 4);
    float v[4] = {v4.x, v4.y, v4.z, v4.w};

    __shared__ float red[8];
    __shared__ float red2[8];
    int lane = tid & 31, wid = tid >> 5;

    float mn = fminf(fminf(v[0], v[1]), fminf(v[2], v[3]));
    mn = warpRedMin(mn);
    if (lane == 0) red[wid] = mn;
    __syncthreads();
    if (tid == 0) {
        float m = red[0];
        #pragma unroll
        for (int w = 1; w < 8; w++) m = fminf(m, red[w]);
        red[0] = m;
    }
    __syncthreads();
    float m = red[0];
    __syncthreads();

    float e1[4], e2[4], s1 = 0.f, s2 = 0.f;
    #pragma unroll
    for (int j = 0; j < 4; j++) {
        float d = v[j] - m;
        e1[j] = __expf(-d);
        e2[j] = __expf(-2.f * d);
        s1 += e1[j]; s2 += e2[j];
    }
    s1 = warpRedSum(s1); s2 = warpRedSum(s2);
    if (lane == 0) { red[wid] = s1; red2[wid] = s2; }
    __syncthreads();
    if (tid == 0) {
        float a = 0.f, b = 0.f;
        #pragma unroll
        for (int w = 0; w < 8; w++) { a += red[w]; b += red2[w]; }
        red[0] = a; red2[0] = b;
    }
    __syncthreads();
    float inv1 = 1.f / red[0];
    float inv2 = 1.f / red2[0];

    __nv_bfloat162 a01 = __floats2bfloat162_rn(e2[0] * inv2, e2[1] * inv2);
    __nv_bfloat162 a23 = __floats2bfloat162_rn(e2[2] * inv2, e2[3] * inv2);
    __nv_bfloat162 l01 = __floats2bfloat162_rn(__logf(e1[0] * inv1 + 1e-10f), __logf(e1[1] * inv1 + 1e-10f));
    __nv_bfloat162 l23 = __floats2bfloat162_rn(__logf(e1[2] * inv1 + 1e-10f), __logf(e1[3] * inv1 + 1e-10f));
    *(__nv_bfloat162*)(adjh + bidx + tid * 4)     = a01;
    *(__nv_bfloat162*)(adjh + bidx + tid * 4 + 2) = a23;
    *(__nv_bfloat162*)(Lh + bidx + tid * 4)       = l01;
    *(__nv_bfloat162*)(Lh + bidx + tid * 4 + 2)   = l23;
}

// ---------------- GEMM2 (HMMA 128x256): fused per-row partial logsumexp ----------------
// Instead of storing S, each CTA emits per row: colmax + sumexp over its 256-col half,
// the diag element, and contributes to the global min.
__global__ __launch_bounds__(256) void k_hmma_scode(int which)
{
    extern __shared__ __align__(16) char sm[];
    uint32_t sb = (uint32_t)__cvta_generic_to_shared(sm);
    int tid = threadIdx.x, wid = tid >> 5, lane = tid & 31;
    int wm = wid & 1, wn = wid >> 1;
    int t = blockIdx.z;
    int i0 = blockIdx.y * 128, j0 = blockIdx.x * 256;

    const __nv_bfloat16* Adj = which ? g_adjVh : g_adjAh;
    const __nv_bfloat16* Lm  = which ? g_LAh   : g_LVh;

    float acc[4][8][4];
    #pragma unroll
    for (int i = 0; i < 4; i++)
        #pragma unroll
        for (int j = 0; j < 8; j++)
            #pragma unroll
            for (int c = 0; c < 4; c++) acc[i][j][c] = 0.f;

    hmma_mainloop(sb,
                  Adj + ((size_t)t * Bb + i0) * Mm,
                  Lm  + ((size_t)t * Bb + j0) * Mm,
                  Mm, Mm / 32, tid, wm, wn, lane, acc);

    __syncthreads();                       // mainloop done; reuse smem
    float* sred = (float*)sm;              // [4][128] per-warp row partials
    float* crm  = sred + 512;              // [128] CTA row max

    int g = lane >> 2, tg = lane & 3;

    // phase 1: row max (per warp over its 64 cols), plus global min
    float thmin = 3.402823466e38f;
    #pragma unroll
    for (int i = 0; i < 4; i++) {
        float mx0 = -3.402823466e38f, mx1 = mx0;
        #pragma unroll
        for (int j = 0; j < 8; j++) {
            mx0 = fmaxf(mx0, fmaxf(acc[i][j][0], acc[i][j][1]));
            mx1 = fmaxf(mx1, fmaxf(acc[i][j][2], acc[i][j][3]));
            thmin = fminf(thmin, fminf(fminf(acc[i][j][0], acc[i][j][1]),
                                       fminf(acc[i][j][2], acc[i][j][3])));
        }
        #pragma unroll
        for (int o = 1; o <= 2; o <<= 1) {
            mx0 = fmaxf(mx0, __shfl_xor_sync(0xffffffffu, mx0, o));
            mx1 = fmaxf(mx1, __shfl_xor_sync(0xffffffffu, mx1, o));
        }
        if (tg == 0) {
            sred[wn * 128 + wm * 64 + i * 16 + g]     = mx0;
            sred[wn * 128 + wm * 64 + i * 16 + g + 8] = mx1;
        }
    }
    __syncthreads();
    if (tid < 128)
        crm[tid] = fmaxf(fmaxf(sred[tid], sred[128 + tid]),
                         fmaxf(sred[256 + tid], sred[384 + tid]));
    __syncthreads();

    // phase 2: sumexp vs CTA row max; diag capture
    #pragma unroll
    for (int i = 0; i < 4; i++) {
        int lr0 = wm * 64 + i * 16 + g;
        int lr1 = lr0 + 8;
        float cm0 = crm[lr0], cm1 = crm[lr1];
        int gr0 = i0 + lr0, gr1 = i0 + lr1;
        float s0 = 0.f, s1 = 0.f;
        #pragma unroll
        for (int j = 0; j < 8; j++) {
            int c = j0 + wn * 64 + j * 8 + tg * 2;
            s0 += __expf(acc[i][j][0] - cm0) + __expf(acc[i][j][1] - cm0);
            s1 += __expf(acc[i][j][2] - cm1) + __expf(acc[i][j][3] - cm1);
            if (c == gr0)     g_diag[(which * Tt + t) * Bb + gr0] = acc[i][j][0];
            if (c + 1 == gr0) g_diag[(which * Tt + t) * Bb + gr0] = acc[i][j][1];
            if (c == gr1)     g_diag[(which * Tt + t) * Bb + gr1] = acc[i][j][2];
            if (c + 1 == gr1) g_diag[(which * Tt + t) * Bb + gr1] = acc[i][j][3];
        }
        #pragma unroll
        for (int o = 1; o <= 2; o <<= 1) {
            s0 += __shfl_xor_sync(0xffffffffu, s0, o);
            s1 += __shfl_xor_sync(0xffffffffu, s1, o);
        }
        if (tg == 0) {
            sred[wn * 128 + lr0] = s0;
            sred[wn * 128 + lr1] = s1;
        }
    }
    __syncthreads();
    if (tid < 128) {
        float s = sred[tid] + sred[128 + tid] + sred[256 + tid] + sred[384 + tid];
        size_t p = (size_t)(((which * Tt + t) * Bb + i0 + tid)) * 2 + (j0 >> 8);
        g_pmax[p] = crm[tid];
        g_psum[p] = s;
    }

    // global min
    __shared__ float redm[8];
    thmin = warpRedMin(thmin);
    if (lane == 0) redm[wid] = thmin;
    __syncthreads();
    if (tid == 0) {
        float m = redm[0];
        #pragma unroll
        for (int w = 1; w < 8; w++) m = fminf(m, redm[w]);
        atomicMin(&g_minkey[which], fenc(m));
    }
}

// ---------------- final loss: combine partials ----------------
__global__ __launch_bounds__(256) void k_loss()
{
    int idx = blockIdx.x * 256 + threadIdx.x;   // 2 * Tt * Bb items
    int w = idx >> 14;                          // Tt*Bb = 16384
    int r = idx & 16383;
    float mn = fdec(g_minkey[w]);
    size_t p = ((size_t)(w * 16384 + r)) * 2;
    double denom = exp((double)(g_pmax[p]     - mn)) * (double)g_psum[p]
                 + exp((double)(g_pmax[p + 1] - mn)) * (double)g_psum[p + 1];
    double term = log(denom + 1e-5) - (double)(g_diag[w * 16384 + r] - mn);

    __shared__ double red[8];
    #pragma unroll
    for (int o = 16; o; o >>= 1) term += __shfl_down_sync(0xffffffffu, term, o);
    int lane = threadIdx.x & 31, wid = threadIdx.x >> 5;
    if (lane == 0) red[wid] = term;
    __syncthreads();
    if (threadIdx.x == 0) {
        double s = 0.0;
        #pragma unroll
        for (int ww = 0; ww < 8; ww++) s += red[ww];
        atomicAdd(&g_acc, s);
    }
}

__global__ void k_final(float* out) {
    out[0] = (float)(g_acc * (1.0 / (2.0 * Tt * Bb)));
}

// ---------------- launch ----------------
extern "C" void kernel_launch(void* const* d_in, const int* in_sizes, int n_in,
                              void* d_out, int out_size)
{
    const float* A = (const float*)d_in[0];
    const float* V = (const float*)d_in[1];
    const float* E = (const float*)d_in[2];
    float* out = (float*)d_out;

    static bool inited = false;
    if (!inited) {
        inited = true;
        cudaFuncSetAttribute(k_hmma_sd,    cudaFuncAttributeMaxDynamicSharedMemorySize, DSM);
        cudaFuncSetAttribute(k_hmma_scode, cudaFuncAttributeMaxDynamicSharedMemorySize, DSM);
    }

    k_init<<<1, 1>>>();
    k_cvt<<<2 * Nn + Mm, 128>>>(A, V, E);

    dim3 g1(Mm / 256, Nn / 128);
    k_hmma_sd<<<g1, 256, DSM>>>(0);
    k_hmma_sd<<<g1, 256, DSM>>>(1);

    k_softmax<<<2 * Nn, 256>>>();

    dim3 g2(Bb / 256, Bb / 128, Tt);
    k_hmma_scode<<<g2, 256, DSM>>>(0);   // adj_a . log(v_pH)^T
    k_hmma_scode<<<g2, 256, DSM>>>(1);   // adj_v . log(a_pH)^T

    k_loss<<<(2 * Tt * Bb) / 256, 256>>>();
    k_final<<<1, 1>>>(out);
}

// round 9
// speedup vs baseline: 6.1403x; 1.3577x over previous
#include <cuda_runtime.h>
#include <cuda_bf16.h>
#include <math.h>
#include <stdint.h>

#define Bb 512
#define Tt 32
#define Dd 512
#define Mm 1024
#define Nn (Bb*Tt)

// ---------------- scratch ----------------
__device__ float g_sdA[(size_t)Nn * Mm];
__device__ float g_sdV[(size_t)Nn * Mm];
__device__ __nv_bfloat16 g_adjAh[(size_t)Nn * Mm];
__device__ __nv_bfloat16 g_LAh [(size_t)Nn * Mm];
__device__ __nv_bfloat16 g_adjVh[(size_t)Nn * Mm];
__device__ __nv_bfloat16 g_LVh [(size_t)Nn * Mm];
__device__ __nv_bfloat16 g_Ah[(size_t)Nn * Dd];
__device__ __nv_bfloat16 g_Vh[(size_t)Nn * Dd];
__device__ __nv_bfloat16 g_Eh[(size_t)Mm * Dd];
__device__ float g_xa[Nn];
__device__ float g_xv[Nn];
__device__ float g_en[Mm];
__device__ float g_pmax[2 * Tt * Bb * 4];   // [which][t][row][jblk] (128-wide blocks)
__device__ float g_psum[2 * Tt * Bb * 4];
__device__ float g_diag[2 * Tt * Bb];
__device__ unsigned g_minkey[2];
__device__ double g_acc;

// ---------------- helpers ----------------
__device__ __forceinline__ unsigned fenc(float f) {
    unsigned u = __float_as_uint(f);
    return (u & 0x80000000u) ? ~u : (u | 0x80000000u);
}
__device__ __forceinline__ float fdec(unsigned u) {
    return __uint_as_float((u & 0x80000000u) ? (u ^ 0x80000000u) : ~u);
}
__device__ __forceinline__ float warpRedSum(float v) {
    #pragma unroll
    for (int o = 16; o; o >>= 1) v += __shfl_down_sync(0xffffffffu, v, o);
    return v;
}
__device__ __forceinline__ float warpRedMin(float v) {
    #pragma unroll
    for (int o = 16; o; o >>= 1) v = fminf(v, __shfl_down_sync(0xffffffffu, v, o));
    return v;
}

__device__ __forceinline__ void cp16(uint32_t s, const void* g) {
    asm volatile("cp.async.cg.shared.global [%0], [%1], 16;"
                 :: "r"(s), "l"(__cvta_generic_to_global(g)) : "memory");
}
#define CP_COMMIT() asm volatile("cp.async.commit_group;" ::: "memory")
#define CP_WAIT1()  asm volatile("cp.async.wait_group 1;" ::: "memory")
#define CP_WAIT0()  asm volatile("cp.async.wait_group 0;" ::: "memory")

#define LDSM4(r0, r1, r2, r3, a) \
    asm volatile("ldmatrix.sync.aligned.m8n8.x4.shared.b16 {%0,%1,%2,%3}, [%4];" \
                 : "=r"(r0), "=r"(r1), "=r"(r2), "=r"(r3) : "r"(a) : "memory")

#define MMA16816(c, a, b) \
    asm volatile("mma.sync.aligned.m16n8k16.row.col.f32.bf16.bf16.f32 " \
                 "{%0,%1,%2,%3}, {%4,%5,%6,%7}, {%8,%9}, {%0,%1,%2,%3};" \
                 : "+f"((c)[0]), "+f"((c)[1]), "+f"((c)[2]), "+f"((c)[3]) \
                 : "r"((a)[0]), "r"((a)[1]), "r"((a)[2]), "r"((a)[3]), \
                   "r"((b)[0]), "r"((b)[1]))

// smem per stage: A(128x32 bf16, 80B rows) + B(128x32 bf16, 80B rows)
#define ROWB 80
#define A_B  (128 * ROWB)            // 10240
#define STAGE (2 * 128 * ROWB)       // 20480
#define NSTG 3
#define DSM (NSTG * STAGE)           // 61440  -> 2 CTAs/SM

// issue one k-tile: A 128x32 + B 128x32 bf16 (4 x 16B per thread)
__device__ __forceinline__ void issue_tile(
    uint32_t st, const __nv_bfloat16* __restrict__ Ag, const __nv_bfloat16* __restrict__ Bg,
    int ld, int k0, int tid)
{
    #pragma unroll
    for (int i = 0; i < 2; i++) {
        int ch = tid + i * 256;
        int row = ch >> 2, c4 = ch & 3;
        cp16(st + (uint32_t)row * ROWB + c4 * 16, Ag + (size_t)row * ld + k0 + c4 * 8);
        cp16(st + A_B + (uint32_t)row * ROWB + c4 * 16, Bg + (size_t)row * ld + k0 + c4 * 8);
    }
    CP_COMMIT();
}

// compute one k32 tile: warp tile 64x32 (wm 0..1, wn 0..3)
__device__ __forceinline__ void compute_tile(
    uint32_t st, int wm, int wn, int lane, float acc[4][4][4])
{
    uint32_t sA = st, sB = st + A_B;
    #pragma unroll
    for (int s = 0; s < 2; s++) {
        uint32_t a[4][4];
        #pragma unroll
        for (int i = 0; i < 4; i++) {
            uint32_t addr = sA + (uint32_t)(wm * 64 + i * 16 + (lane & 15)) * ROWB
                          + s * 32 + (lane >> 4) * 16;
            LDSM4(a[i][0], a[i][1], a[i][2], a[i][3], addr);
        }
        uint32_t b[4][2];
        #pragma unroll
        for (int jj = 0; jj < 2; jj++) {
            uint32_t addr = sB + (uint32_t)(wn * 32 + jj * 16 + ((lane >> 4) * 8 + (lane & 7))) * ROWB
                          + ((lane >> 3) & 1) * 16 + s * 32;
            uint32_t r0, r1, r2, r3;
            LDSM4(r0, r1, r2, r3, addr);
            b[jj * 2][0] = r0;     b[jj * 2][1] = r1;
            b[jj * 2 + 1][0] = r2; b[jj * 2 + 1][1] = r3;
        }
        #pragma unroll
        for (int i = 0; i < 4; i++)
            #pragma unroll
            for (int j = 0; j < 4; j++)
                MMA16816(acc[i][j], a[i], b[j]);
    }
}

// 3-stage pipelined mainloop, one __syncthreads per k-tile
__device__ __forceinline__ void hmma_mainloop(
    uint32_t sb, const __nv_bfloat16* __restrict__ Ag, const __nv_bfloat16* __restrict__ Bg,
    int ld, int NT, int tid, int wm, int wn, int lane, float acc[4][4][4])
{
    issue_tile(sb, Ag, Bg, ld, 0, tid);
    issue_tile(sb + STAGE, Ag, Bg, ld, 32, tid);
    for (int kt = 0; kt < NT; kt++) {
        if (kt + 1 < NT) CP_WAIT1(); else CP_WAIT0();
        __syncthreads();
        if (kt + 2 < NT)
            issue_tile(sb + ((kt + 2) % 3) * STAGE, Ag, Bg, ld, (kt + 2) * 32, tid);
        compute_tile(sb + (kt % 3) * STAGE, wm, wn, lane, acc);
    }
}

// ---------------- init ----------------
__global__ void k_init() {
    g_minkey[0] = 0xFFFFFFFFu;
    g_minkey[1] = 0xFFFFFFFFu;
    g_acc = 0.0;
}

// ---------------- fused fp32->bf16 convert + row squared-norm ----------------
__global__ __launch_bounds__(128) void k_cvt(
    const float* __restrict__ A, const float* __restrict__ V, const float* __restrict__ E)
{
    int row = blockIdx.x;
    const float* src; __nv_bfloat16* dst; float* nrm; int r;
    if (row < Nn)          { src = A; dst = g_Ah; nrm = g_xa; r = row; }
    else if (row < 2 * Nn) { src = V; dst = g_Vh; nrm = g_xv; r = row - Nn; }
    else                   { src = E; dst = g_Eh; nrm = g_en; r = row - 2 * Nn; }

    int t = threadIdx.x;
    float4 v = *(const float4*)(src + (size_t)r * Dd + t * 4);
    float s = v.x * v.x + v.y * v.y + v.z * v.z + v.w * v.w;

    __nv_bfloat162 lo = __floats2bfloat162_rn(v.x, v.y);
    __nv_bfloat162 hi = __floats2bfloat162_rn(v.z, v.w);
    uint2 pk;
    pk.x = *(unsigned*)&lo;
    pk.y = *(unsigned*)&hi;
    *(uint2*)(dst + (size_t)r * Dd + t * 4) = pk;

    __shared__ float red[4];
    s = warpRedSum(s);
    int lane = t & 31, wid = t >> 5;
    if (lane == 0) red[wid] = s;
    __syncthreads();
    if (t == 0) nrm[r] = red[0] + red[1] + red[2] + red[3];
}

// ---------------- GEMM1 (HMMA 128x128): sd -> (T,B,M); which in blockIdx.z ----------------
__global__ __launch_bounds__(256, 2) void k_hmma_sd()
{
    extern __shared__ __align__(16) char sm[];
    uint32_t sb = (uint32_t)__cvta_generic_to_shared(sm);
    int tid = threadIdx.x, wid = tid >> 5, lane = tid & 31;
    int wm = wid & 1, wn = wid >> 1;
    int which = blockIdx.z;
    int m0 = blockIdx.x * 128, n0 = blockIdx.y * 128;

    const __nv_bfloat16* X = which ? g_Vh : g_Ah;
    const float* xn2 = which ? g_xv : g_xa;
    float* outsd = which ? g_sdV : g_sdA;

    float acc[4][4][4];
    #pragma unroll
    for (int i = 0; i < 4; i++)
        #pragma unroll
        for (int j = 0; j < 4; j++)
            #pragma unroll
            for (int c = 0; c < 4; c++) acc[i][j][c] = 0.f;

    hmma_mainloop(sb, X + (size_t)n0 * Dd, g_Eh + (size_t)m0 * Dd, Dd, Dd / 32,
                  tid, wm, wn, lane, acc);

    int g = lane >> 2, tg = lane & 3;
    #pragma unroll
    for (int i = 0; i < 4; i++) {
        int n_lo = n0 + wm * 64 + i * 16 + g;
        int n_hi = n_lo + 8;
        float xlo = xn2[n_lo], xhi = xn2[n_hi];
        float* rl = outsd + ((size_t)((n_lo & 31) * Bb + (n_lo >> 5))) * Mm;
        float* rh = outsd + ((size_t)((n_hi & 31) * Bb + (n_hi >> 5))) * Mm;
        #pragma unroll
        for (int j = 0; j < 4; j++) {
            int m = m0 + wn * 32 + j * 8 + tg * 2;
            float e0 = g_en[m], e1 = g_en[m + 1];
            float2 lo, hi;
            lo.x = sqrtf(fmaxf(fmaf(-2.f, acc[i][j][0], xlo + e0), 0.f));
            lo.y = sqrtf(fmaxf(fmaf(-2.f, acc[i][j][1], xlo + e1), 0.f));
            hi.x = sqrtf(fmaxf(fmaf(-2.f, acc[i][j][2], xhi + e0), 0.f));
            hi.y = sqrtf(fmaxf(fmaf(-2.f, acc[i][j][3], xhi + e1), 0.f));
            *(float2*)(rl + m) = lo;
            *(float2*)(rh + m) = hi;
        }
    }
}

// ---------------- double softmax per row -> bf16 adj + bf16 log(pH) ----------------
__global__ __launch_bounds__(256) void k_softmax()
{
    int row = blockIdx.x;
    const float* sd; __nv_bfloat16 *adjh, *Lh;
    if (row < Nn) { sd = g_sdA; adjh = g_adjAh; Lh = g_LAh; }
    else          { sd = g_sdV; adjh = g_adjVh; Lh = g_LVh; row -= Nn; }

    int tid = threadIdx.x;
    size_t bidx = (size_t)row * Mm;
    float4 v4 = *(const float4*)(sd + bidx + tid * 4);
    float v[4] = {v4.x, v4.y, v4.z, v4.w};

    __shared__ float red[8];
    __shared__ float red2[8];
    int lane = tid & 31, wid = tid >> 5;

    float mn = fminf(fminf(v[0], v[1]), fminf(v[2], v[3]));
    mn = warpRedMin(mn);
    if (lane == 0) red[wid] = mn;
    __syncthreads();
    if (tid == 0) {
        float m = red[0];
        #pragma unroll
        for (int w = 1; w < 8; w++) m = fminf(m, red[w]);
        red[0] = m;
    }
    __syncthreads();
    float m = red[0];
    __syncthreads();

    float e1[4], e2[4], s1 = 0.f, s2 = 0.f;
    #pragma unroll
    for (int j = 0; j < 4; j++) {
        float d = v[j] - m;
        e1[j] = __expf(-d);
        e2[j] = __expf(-2.f * d);
        s1 += e1[j]; s2 += e2[j];
    }
    s1 = warpRedSum(s1); s2 = warpRedSum(s2);
    if (lane == 0) { red[wid] = s1; red2[wid] = s2; }
    __syncthreads();
    if (tid == 0) {
        float a = 0.f, b = 0.f;
        #pragma unroll
        for (int w = 0; w < 8; w++) { a += red[w]; b += red2[w]; }
        red[0] = a; red2[0] = b;
    }
    __syncthreads();
    float inv1 = 1.f / red[0];
    float inv2 = 1.f / red2[0];

    __nv_bfloat162 a01 = __floats2bfloat162_rn(e2[0] * inv2, e2[1] * inv2);
    __nv_bfloat162 a23 = __floats2bfloat162_rn(e2[2] * inv2, e2[3] * inv2);
    __nv_bfloat162 l01 = __floats2bfloat162_rn(__logf(e1[0] * inv1 + 1e-10f), __logf(e1[1] * inv1 + 1e-10f));
    __nv_bfloat162 l23 = __floats2bfloat162_rn(__logf(e1[2] * inv1 + 1e-10f), __logf(e1[3] * inv1 + 1e-10f));
    *(__nv_bfloat162*)(adjh + bidx + tid * 4)     = a01;
    *(__nv_bfloat162*)(adjh + bidx + tid * 4 + 2) = a23;
    *(__nv_bfloat162*)(Lh + bidx + tid * 4)       = l01;
    *(__nv_bfloat162*)(Lh + bidx + tid * 4 + 2)   = l23;
}

// ---------------- GEMM2 (HMMA 128x128): fused per-row partial logsumexp ----------------
// blockIdx.z in [0, 2*Tt): which = z >= Tt, t = z % Tt.
__global__ __launch_bounds__(256, 2) void k_hmma_scode()
{
    extern __shared__ __align__(16) char sm[];
    uint32_t sb = (uint32_t)__cvta_generic_to_shared(sm);
    int tid = threadIdx.x, wid = tid >> 5, lane = tid & 31;
    int wm = wid & 1, wn = wid >> 1;
    int z = blockIdx.z;
    int which = z >= Tt;
    int t = z & (Tt - 1);
    int i0 = blockIdx.y * 128, j0 = blockIdx.x * 128;

    const __nv_bfloat16* Adj = which ? g_adjVh : g_adjAh;
    const __nv_bfloat16* Lm  = which ? g_LAh   : g_LVh;

    float acc[4][4][4];
    #pragma unroll
    for (int i = 0; i < 4; i++)
        #pragma unroll
        for (int j = 0; j < 4; j++)
            #pragma unroll
            for (int c = 0; c < 4; c++) acc[i][j][c] = 0.f;

    hmma_mainloop(sb,
                  Adj + ((size_t)t * Bb + i0) * Mm,
                  Lm  + ((size_t)t * Bb + j0) * Mm,
                  Mm, Mm / 32, tid, wm, wn, lane, acc);

    __syncthreads();                       // mainloop done; reuse smem
    float* sred = (float*)sm;              // [4][128]
    float* crm  = sred + 512;              // [128]

    int g = lane >> 2, tg = lane & 3;

    // phase 1: row max over warp's 32 cols; global min
    float thmin = 3.402823466e38f;
    #pragma unroll
    for (int i = 0; i < 4; i++) {
        float mx0 = -3.402823466e38f, mx1 = mx0;
        #pragma unroll
        for (int j = 0; j < 4; j++) {
            mx0 = fmaxf(mx0, fmaxf(acc[i][j][0], acc[i][j][1]));
            mx1 = fmaxf(mx1, fmaxf(acc[i][j][2], acc[i][j][3]));
            thmin = fminf(thmin, fminf(fminf(acc[i][j][0], acc[i][j][1]),
                                       fminf(acc[i][j][2], acc[i][j][3])));
        }
        #pragma unroll
        for (int o = 1; o <= 2; o <<= 1) {
            mx0 = fmaxf(mx0, __shfl_xor_sync(0xffffffffu, mx0, o));
            mx1 = fmaxf(mx1, __shfl_xor_sync(0xffffffffu, mx1, o));
        }
        if (tg == 0) {
            sred[wn * 128 + wm * 64 + i * 16 + g]     = mx0;
            sred[wn * 128 + wm * 64 + i * 16 + g + 8] = mx1;
        }
    }
    __syncthreads();
    if (tid < 128)
        crm[tid] = fmaxf(fmaxf(sred[tid], sred[128 + tid]),
                         fmaxf(sred[256 + tid], sred[384 + tid]));
    __syncthreads();

    // phase 2: sumexp vs CTA row max; diag capture
    #pragma unroll
    for (int i = 0; i < 4; i++) {
        int lr0 = wm * 64 + i * 16 + g;
        int lr1 = lr0 + 8;
        float cm0 = crm[lr0], cm1 = crm[lr1];
        int gr0 = i0 + lr0, gr1 = i0 + lr1;
        float s0 = 0.f, s1 = 0.f;
        #pragma unroll
        for (int j = 0; j < 4; j++) {
            int c = j0 + wn * 32 + j * 8 + tg * 2;
            s0 += __expf(acc[i][j][0] - cm0) + __expf(acc[i][j][1] - cm0);
            s1 += __expf(acc[i][j][2] - cm1) + __expf(acc[i][j][3] - cm1);
            if (c == gr0)     g_diag[(which * Tt + t) * Bb + gr0] = acc[i][j][0];
            if (c + 1 == gr0) g_diag[(which * Tt + t) * Bb + gr0] = acc[i][j][1];
            if (c == gr1)     g_diag[(which * Tt + t) * Bb + gr1] = acc[i][j][2];
            if (c + 1 == gr1) g_diag[(which * Tt + t) * Bb + gr1] = acc[i][j][3];
        }
        #pragma unroll
        for (int o = 1; o <= 2; o <<= 1) {
            s0 += __shfl_xor_sync(0xffffffffu, s0, o);
            s1 += __shfl_xor_sync(0xffffffffu, s1, o);
        }
        if (tg == 0) {
            sred[wn * 128 + lr0] = s0;
            sred[wn * 128 + lr1] = s1;
        }
    }
    __syncthreads();
    if (tid < 128) {
        float s = sred[tid] + sred[128 + tid] + sred[256 + tid] + sred[384 + tid];
        size_t p = (size_t)(((which * Tt + t) * Bb + i0 + tid)) * 4 + (j0 >> 7);
        g_pmax[p] = crm[tid];
        g_psum[p] = s;
    }

    // global min
    __shared__ float redm[8];
    thmin = warpRedMin(thmin);
    if (lane == 0) redm[wid] = thmin;
    __syncthreads();
    if (tid == 0) {
        float m = redm[0];
        #pragma unroll
        for (int w = 1; w < 8; w++) m = fminf(m, redm[w]);
        atomicMin(&g_minkey[which], fenc(m));
    }
}

// ---------------- final loss: combine 4 partials per row ----------------
__global__ __launch_bounds__(256) void k_loss()
{
    int idx = blockIdx.x * 256 + threadIdx.x;   // 2 * Tt * Bb items
    int w = idx >> 14;                          // Tt*Bb = 16384
    int r = idx & 16383;
    float mn = fdec(g_minkey[w]);
    size_t p = ((size_t)(w * 16384 + r)) * 4;
    double denom = 0.0;
    #pragma unroll
    for (int q = 0; q < 4; q++)
        denom += exp((double)(g_pmax[p + q] - mn)) * (double)g_psum[p + q];
    double term = log(denom + 1e-5) - (double)(g_diag[w * 16384 + r] - mn);

    __shared__ double red[8];
    #pragma unroll
    for (int o = 16; o; o >>= 1) term += __shfl_down_sync(0xffffffffu, term, o);
    int lane = threadIdx.x & 31, wid = threadIdx.x >> 5;
    if (lane == 0) red[wid] = term;
    __syncthreads();
    if (threadIdx.x == 0) {
        double s = 0.0;
        #pragma unroll
        for (int ww = 0; ww < 8; ww++) s += red[ww];
        atomicAdd(&g_acc, s);
    }
}

__global__ void k_final(float* out) {
    out[0] = (float)(g_acc * (1.0 / (2.0 * Tt * Bb)));
}

// ---------------- launch ----------------
extern "C" void kernel_launch(void* const* d_in, const int* in_sizes, int n_in,
                              void* d_out, int out_size)
{
    const float* A = (const float*)d_in[0];
    const float* V = (const float*)d_in[1];
    const float* E = (const float*)d_in[2];
    float* out = (float*)d_out;

    static bool inited = false;
    if (!inited) {
        inited = true;
        cudaFuncSetAttribute(k_hmma_sd,    cudaFuncAttributeMaxDynamicSharedMemorySize, DSM);
        cudaFuncSetAttribute(k_hmma_scode, cudaFuncAttributeMaxDynamicSharedMemorySize, DSM);
    }

    k_init<<<1, 1>>>();
    k_cvt<<<2 * Nn + Mm, 128>>>(A, V, E);

    dim3 g1(Mm / 128, Nn / 128, 2);
    k_hmma_sd<<<g1, 256, DSM>>>();

    k_softmax<<<2 * Nn, 256>>>();

    dim3 g2(Bb / 128, Bb / 128, 2 * Tt);
    k_hmma_scode<<<g2, 256, DSM>>>();

    k_loss<<<(2 * Tt * Bb) / 256, 256>>>();
    k_final<<<1, 1>>>(out);
}

// round 11
// speedup vs baseline: 6.5340x; 1.0641x over previous
#include <cuda_runtime.h>
#include <cuda_bf16.h>
#include <math.h>
#include <stdint.h>

#define Bb 512
#define Tt 32
#define Dd 512
#define Mm 1024
#define Nn (Bb*Tt)

// ---------------- scratch ----------------
__device__ float g_sdA[(size_t)Nn * Mm];
__device__ float g_sdV[(size_t)Nn * Mm];
__device__ __nv_bfloat16 g_adjAh[(size_t)Nn * Mm];
__device__ __nv_bfloat16 g_LAh [(size_t)Nn * Mm];
__device__ __nv_bfloat16 g_adjVh[(size_t)Nn * Mm];
__device__ __nv_bfloat16 g_LVh [(size_t)Nn * Mm];
__device__ __nv_bfloat16 g_Ah[(size_t)Nn * Dd];
__device__ __nv_bfloat16 g_Vh[(size_t)Nn * Dd];
__device__ __nv_bfloat16 g_Eh[(size_t)Mm * Dd];
__device__ float g_xa[Nn];
__device__ float g_xv[Nn];
__device__ float g_en[Mm];
__device__ float g_pmax[2 * Tt * Bb * 4];   // [which][t][row][jblk]
__device__ float g_psum[2 * Tt * Bb * 4];
__device__ float g_diag[2 * Tt * Bb];
__device__ unsigned g_minkey[2];
__device__ double g_acc;

// ---------------- helpers ----------------
__device__ __forceinline__ unsigned fenc(float f) {
    unsigned u = __float_as_uint(f);
    return (u & 0x80000000u) ? ~u : (u | 0x80000000u);
}
__device__ __forceinline__ float fdec(unsigned u) {
    return __uint_as_float((u & 0x80000000u) ? (u ^ 0x80000000u) : ~u);
}
__device__ __forceinline__ float warpRedSum(float v) {
    #pragma unroll
    for (int o = 16; o; o >>= 1) v += __shfl_down_sync(0xffffffffu, v, o);
    return v;
}
__device__ __forceinline__ float warpRedMin(float v) {
    #pragma unroll
    for (int o = 16; o; o >>= 1) v = fminf(v, __shfl_down_sync(0xffffffffu, v, o));
    return v;
}

__device__ __forceinline__ void cp16(uint32_t s, const void* g) {
    asm volatile("cp.async.cg.shared.global [%0], [%1], 16;"
                 :: "r"(s), "l"(__cvta_generic_to_global(g)) : "memory");
}
#define CP_COMMIT() asm volatile("cp.async.commit_group;" ::: "memory")
#define CP_WAIT1()  asm volatile("cp.async.wait_group 1;" ::: "memory")
#define CP_WAIT0()  asm volatile("cp.async.wait_group 0;" ::: "memory")

#define LDSM4(r0, r1, r2, r3, a) \
    asm volatile("ldmatrix.sync.aligned.m8n8.x4.shared.b16 {%0,%1,%2,%3}, [%4];" \
                 : "=r"(r0), "=r"(r1), "=r"(r2), "=r"(r3) : "r"(a) : "memory")

#define MMA16816(c, a, b) \
    asm volatile("mma.sync.aligned.m16n8k16.row.col.f32.bf16.bf16.f32 " \
                 "{%0,%1,%2,%3}, {%4,%5,%6,%7}, {%8,%9}, {%0,%1,%2,%3};" \
                 : "+f"((c)[0]), "+f"((c)[1]), "+f"((c)[2]), "+f"((c)[3]) \
                 : "r"((a)[0]), "r"((a)[1]), "r"((a)[2]), "r"((a)[3]), \
                   "r"((b)[0]), "r"((b)[1]))

#define ROWB 80
#define A_B  (128 * ROWB)
#define STAGE (2 * 128 * ROWB)       // 20480
#define NSTG 3
#define DSM (NSTG * STAGE)           // 61440 -> 2 CTAs/SM

__device__ __forceinline__ void issue_tile(
    uint32_t st, const __nv_bfloat16* __restrict__ Ag, const __nv_bfloat16* __restrict__ Bg,
    int ld, int k0, int tid)
{
    #pragma unroll
    for (int i = 0; i < 2; i++) {
        int ch = tid + i * 256;
        int row = ch >> 2, c4 = ch & 3;
        cp16(st + (uint32_t)row * ROWB + c4 * 16, Ag + (size_t)row * ld + k0 + c4 * 8);
        cp16(st + A_B + (uint32_t)row * ROWB + c4 * 16, Bg + (size_t)row * ld + k0 + c4 * 8);
    }
    CP_COMMIT();
}

__device__ __forceinline__ void compute_tile(
    uint32_t st, int wm, int wn, int lane, float acc[4][4][4])
{
    uint32_t sA = st, sB = st + A_B;
    #pragma unroll
    for (int s = 0; s < 2; s++) {
        uint32_t a[4][4];
        #pragma unroll
        for (int i = 0; i < 4; i++) {
            uint32_t addr = sA + (uint32_t)(wm * 64 + i * 16 + (lane & 15)) * ROWB
                          + s * 32 + (lane >> 4) * 16;
            LDSM4(a[i][0], a[i][1], a[i][2], a[i][3], addr);
        }
        uint32_t b[4][2];
        #pragma unroll
        for (int jj = 0; jj < 2; jj++) {
            uint32_t addr = sB + (uint32_t)(wn * 32 + jj * 16 + ((lane >> 4) * 8 + (lane & 7))) * ROWB
                          + ((lane >> 3) & 1) * 16 + s * 32;
            uint32_t r0, r1, r2, r3;
            LDSM4(r0, r1, r2, r3, addr);
            b[jj * 2][0] = r0;     b[jj * 2][1] = r1;
            b[jj * 2 + 1][0] = r2; b[jj * 2 + 1][1] = r3;
        }
        #pragma unroll
        for (int i = 0; i < 4; i++)
            #pragma unroll
            for (int j = 0; j < 4; j++)
                MMA16816(acc[i][j], a[i], b[j]);
    }
}

__device__ __forceinline__ void hmma_mainloop(
    uint32_t sb, const __nv_bfloat16* __restrict__ Ag, const __nv_bfloat16* __restrict__ Bg,
    int ld, int NT, int tid, int wm, int wn, int lane, float acc[4][4][4])
{
    issue_tile(sb, Ag, Bg, ld, 0, tid);
    issue_tile(sb + STAGE, Ag, Bg, ld, 32, tid);
    for (int kt = 0; kt < NT; kt++) {
        if (kt + 1 < NT) CP_WAIT1(); else CP_WAIT0();
        __syncthreads();
        if (kt + 2 < NT)
            issue_tile(sb + ((kt + 2) % 3) * STAGE, Ag, Bg, ld, (kt + 2) * 32, tid);
        compute_tile(sb + (kt % 3) * STAGE, wm, wn, lane, acc);
    }
}

// ---------------- init ----------------
__global__ void k_init() {
    g_minkey[0] = 0xFFFFFFFFu;
    g_minkey[1] = 0xFFFFFFFFu;
    g_acc = 0.0;
}

// ---------------- fused fp32->bf16 convert + row squared-norm ----------------
__global__ __launch_bounds__(128) void k_cvt(
    const float* __restrict__ A, const float* __restrict__ V, const float* __restrict__ E)
{
    int row = blockIdx.x;
    const float* src; __nv_bfloat16* dst; float* nrm; int r;
    if (row < Nn)          { src = A; dst = g_Ah; nrm = g_xa; r = row; }
    else if (row < 2 * Nn) { src = V; dst = g_Vh; nrm = g_xv; r = row - Nn; }
    else                   { src = E; dst = g_Eh; nrm = g_en; r = row - 2 * Nn; }

    int t = threadIdx.x;
    float4 v = *(const float4*)(src + (size_t)r * Dd + t * 4);
    float s = v.x * v.x + v.y * v.y + v.z * v.z + v.w * v.w;

    __nv_bfloat162 lo = __floats2bfloat162_rn(v.x, v.y);
    __nv_bfloat162 hi = __floats2bfloat162_rn(v.z, v.w);
    uint2 pk;
    pk.x = *(unsigned*)&lo;
    pk.y = *(unsigned*)&hi;
    *(uint2*)(dst + (size_t)r * Dd + t * 4) = pk;

    __shared__ float red[4];
    s = warpRedSum(s);
    int lane = t & 31, wid = t >> 5;
    if (lane == 0) red[wid] = s;
    __syncthreads();
    if (t == 0) nrm[r] = red[0] + red[1] + red[2] + red[3];
}

// ---------------- GEMM1 (HMMA 128x128): sd -> (T,B,M); which in blockIdx.z ----------------
__global__ __launch_bounds__(256, 2) void k_hmma_sd()
{
    extern __shared__ __align__(16) char sm[];
    uint32_t sb = (uint32_t)__cvta_generic_to_shared(sm);
    int tid = threadIdx.x, wid = tid >> 5, lane = tid & 31;
    int wm = wid & 1, wn = wid >> 1;
    int which = blockIdx.z;
    int m0 = blockIdx.x * 128, n0 = blockIdx.y * 128;

    const __nv_bfloat16* X = which ? g_Vh : g_Ah;
    const float* xn2 = which ? g_xv : g_xa;
    float* outsd = which ? g_sdV : g_sdA;

    float acc[4][4][4];
    #pragma unroll
    for (int i = 0; i < 4; i++)
        #pragma unroll
        for (int j = 0; j < 4; j++)
            #pragma unroll
            for (int c = 0; c < 4; c++) acc[i][j][c] = 0.f;

    hmma_mainloop(sb, X + (size_t)n0 * Dd, g_Eh + (size_t)m0 * Dd, Dd, Dd / 32,
                  tid, wm, wn, lane, acc);

    int g = lane >> 2, tg = lane & 3;
    #pragma unroll
    for (int i = 0; i < 4; i++) {
        int n_lo = n0 + wm * 64 + i * 16 + g;
        int n_hi = n_lo + 8;
        float xlo = xn2[n_lo], xhi = xn2[n_hi];
        float* rl = outsd + ((size_t)((n_lo & 31) * Bb + (n_lo >> 5))) * Mm;
        float* rh = outsd + ((size_t)((n_hi & 31) * Bb + (n_hi >> 5))) * Mm;
        #pragma unroll
        for (int j = 0; j < 4; j++) {
            int m = m0 + wn * 32 + j * 8 + tg * 2;
            float e0 = g_en[m], e1 = g_en[m + 1];
            float2 lo, hi;
            lo.x = sqrtf(fmaxf(fmaf(-2.f, acc[i][j][0], xlo + e0), 0.f));
            lo.y = sqrtf(fmaxf(fmaf(-2.f, acc[i][j][1], xlo + e1), 0.f));
            hi.x = sqrtf(fmaxf(fmaf(-2.f, acc[i][j][2], xhi + e0), 0.f));
            hi.y = sqrtf(fmaxf(fmaf(-2.f, acc[i][j][3], xhi + e1), 0.f));
            *(float2*)(rl + m) = lo;
            *(float2*)(rh + m) = hi;
        }
    }
}

// ---------------- softmax: one warp per row, single exp per element ----------------
// adj = e1^2 / s2 ;  L = (m - log s1) - v   (1e-10 negligible: p ~ 1e-3 >> 1e-10)
__global__ __launch_bounds__(256) void k_softmax()
{
    int row = blockIdx.x * 8 + (threadIdx.x >> 5);
    int lane = threadIdx.x & 31;
    const float* sd; __nv_bfloat16 *adjh, *Lh;
    if (row < Nn) { sd = g_sdA; adjh = g_adjAh; Lh = g_LAh; }
    else          { sd = g_sdV; adjh = g_adjVh; Lh = g_LVh; row -= Nn; }

    size_t base = (size_t)row * Mm;
    float4 v[8];
    #pragma unroll
    for (int k = 0; k < 8; k++)
        v[k] = *(const float4*)(sd + base + ((size_t)(k * 32 + lane)) * 4);

    // row min
    float mn = 3.402823466e38f;
    #pragma unroll
    for (int k = 0; k < 8; k++)
        mn = fminf(mn, fminf(fminf(v[k].x, v[k].y), fminf(v[k].z, v[k].w)));
    #pragma unroll
    for (int o = 16; o; o >>= 1) mn = fminf(mn, __shfl_xor_sync(0xffffffffu, mn, o));

    // e1 = exp(-(v-mn)); s1 = sum e1; s2 = sum e1^2
    float4 e1[8];
    float s1 = 0.f, s2 = 0.f;
    #pragma unroll
    for (int k = 0; k < 8; k++) {
        e1[k].x = __expf(mn - v[k].x);
        e1[k].y = __expf(mn - v[k].y);
        e1[k].z = __expf(mn - v[k].z);
        e1[k].w = __expf(mn - v[k].w);
        s1 += e1[k].x + e1[k].y + e1[k].z + e1[k].w;
        s2 += e1[k].x * e1[k].x + e1[k].y * e1[k].y
            + e1[k].z * e1[k].z + e1[k].w * e1[k].w;
    }
    #pragma unroll
    for (int o = 16; o; o >>= 1) {
        s1 += __shfl_xor_sync(0xffffffffu, s1, o);
        s2 += __shfl_xor_sync(0xffffffffu, s2, o);
    }
    float inv2 = 1.f / s2;
    float c = mn - __logf(s1);   // L_j = c - v_j

    #pragma unroll
    for (int k = 0; k < 8; k++) {
        size_t off = base + ((size_t)(k * 32 + lane)) * 4;
        __nv_bfloat162 a01 = __floats2bfloat162_rn(e1[k].x * e1[k].x * inv2,
                                                   e1[k].y * e1[k].y * inv2);
        __nv_bfloat162 a23 = __floats2bfloat162_rn(e1[k].z * e1[k].z * inv2,
                                                   e1[k].w * e1[k].w * inv2);
        __nv_bfloat162 l01 = __floats2bfloat162_rn(c - v[k].x, c - v[k].y);
        __nv_bfloat162 l23 = __floats2bfloat162_rn(c - v[k].z, c - v[k].w);
        uint2 pa, pl;
        pa.x = *(unsigned*)&a01; pa.y = *(unsigned*)&a23;
        pl.x = *(unsigned*)&l01; pl.y = *(unsigned*)&l23;
        *(uint2*)(adjh + off) = pa;
        *(uint2*)(Lh + off)   = pl;
    }
}

// ---------------- GEMM2 (HMMA 128x128): fused per-row partial logsumexp ----------------
__global__ __launch_bounds__(256, 2) void k_hmma_scode()
{
    extern __shared__ __align__(16) char sm[];
    uint32_t sb = (uint32_t)__cvta_generic_to_shared(sm);
    int tid = threadIdx.x, wid = tid >> 5, lane = tid & 31;
    int wm = wid & 1, wn = wid >> 1;
    int z = blockIdx.z;
    int which = z >= Tt;
    int t = z & (Tt - 1);
    int i0 = blockIdx.y * 128, j0 = blockIdx.x * 128;

    const __nv_bfloat16* Adj = which ? g_adjVh : g_adjAh;
    const __nv_bfloat16* Lm  = which ? g_LAh   : g_LVh;

    float acc[4][4][4];
    #pragma unroll
    for (int i = 0; i < 4; i++)
        #pragma unroll
        for (int j = 0; j < 4; j++)
            #pragma unroll
            for (int c = 0; c < 4; c++) acc[i][j][c] = 0.f;

    hmma_mainloop(sb,
                  Adj + ((size_t)t * Bb + i0) * Mm,
                  Lm  + ((size_t)t * Bb + j0) * Mm,
                  Mm, Mm / 32, tid, wm, wn, lane, acc);

    __syncthreads();
    float* sred = (float*)sm;              // [4][128]
    float* crm  = sred + 512;              // [128]

    int g = lane >> 2, tg = lane & 3;

    float thmin = 3.402823466e38f;
    #pragma unroll
    for (int i = 0; i < 4; i++) {
        float mx0 = -3.402823466e38f, mx1 = mx0;
        #pragma unroll
        for (int j = 0; j < 4; j++) {
            mx0 = fmaxf(mx0, fmaxf(acc[i][j][0], acc[i][j][1]));
            mx1 = fmaxf(mx1, fmaxf(acc[i][j][2], acc[i][j][3]));
            thmin = fminf(thmin, fminf(fminf(acc[i][j][0], acc[i][j][1]),
                                       fminf(acc[i][j][2], acc[i][j][3])));
        }
        #pragma unroll
        for (int o = 1; o <= 2; o <<= 1) {
            mx0 = fmaxf(mx0, __shfl_xor_sync(0xffffffffu, mx0, o));
            mx1 = fmaxf(mx1, __shfl_xor_sync(0xffffffffu, mx1, o));
        }
        if (tg == 0) {
            sred[wn * 128 + wm * 64 + i * 16 + g]     = mx0;
            sred[wn * 128 + wm * 64 + i * 16 + g + 8] = mx1;
        }
    }
    __syncthreads();
    if (tid < 128)
        crm[tid] = fmaxf(fmaxf(sred[tid], sred[128 + tid]),
                         fmaxf(sred[256 + tid], sred[384 + tid]));
    __syncthreads();

    #pragma unroll
    for (int i = 0; i < 4; i++) {
        int lr0 = wm * 64 + i * 16 + g;
        int lr1 = lr0 + 8;
        float cm0 = crm[lr0], cm1 = crm[lr1];
        int gr0 = i0 + lr0, gr1 = i0 + lr1;
        float s0 = 0.f, s1 = 0.f;
        #pragma unroll
        for (int j = 0; j < 4; j++) {
            int c = j0 + wn * 32 + j * 8 + tg * 2;
            s0 += __expf(acc[i][j][0] - cm0) + __expf(acc[i][j][1] - cm0);
            s1 += __expf(acc[i][j][2] - cm1) + __expf(acc[i][j][3] - cm1);
            if (c == gr0)     g_diag[(which * Tt + t) * Bb + gr0] = acc[i][j][0];
            if (c + 1 == gr0) g_diag[(which * Tt + t) * Bb + gr0] = acc[i][j][1];
            if (c == gr1)     g_diag[(which * Tt + t) * Bb + gr1] = acc[i][j][2];
            if (c + 1 == gr1) g_diag[(which * Tt + t) * Bb + gr1] = acc[i][j][3];
        }
        #pragma unroll
        for (int o = 1; o <= 2; o <<= 1) {
            s0 += __shfl_xor_sync(0xffffffffu, s0, o);
            s1 += __shfl_xor_sync(0xffffffffu, s1, o);
        }
        if (tg == 0) {
            sred[wn * 128 + lr0] = s0;
            sred[wn * 128 + lr1] = s1;
        }
    }
    __syncthreads();
    if (tid < 128) {
        float s = sred[tid] + sred[128 + tid] + sred[256 + tid] + sred[384 + tid];
        size_t p = (size_t)(((which * Tt + t) * Bb + i0 + tid)) * 4 + (j0 >> 7);
        g_pmax[p] = crm[tid];
        g_psum[p] = s;
    }

    __shared__ float redm[8];
    thmin = warpRedMin(thmin);
    if (lane == 0) redm[wid] = thmin;
    __syncthreads();
    if (tid == 0) {
        float m = redm[0];
        #pragma unroll
        for (int w = 1; w < 8; w++) m = fminf(m, redm[w]);
        atomicMin(&g_minkey[which], fenc(m));
    }
}

// ---------------- final loss ----------------
__global__ __launch_bounds__(256) void k_loss()
{
    int idx = blockIdx.x * 256 + threadIdx.x;
    int w = idx >> 14;
    int r = idx & 16383;
    float mn = fdec(g_minkey[w]);
    size_t p = ((size_t)(w * 16384 + r)) * 4;
    double denom = 0.0;
    #pragma unroll
    for (int q = 0; q < 4; q++)
        denom += exp((double)(g_pmax[p + q] - mn)) * (double)g_psum[p + q];
    double term = log(denom + 1e-5) - (double)(g_diag[w * 16384 + r] - mn);

    __shared__ double red[8];
    #pragma unroll
    for (int o = 16; o; o >>= 1) term += __shfl_down_sync(0xffffffffu, term, o);
    int lane = threadIdx.x & 31, wid = threadIdx.x >> 5;
    if (lane == 0) red[wid] = term;
    __syncthreads();
    if (threadIdx.x == 0) {
        double s = 0.0;
        #pragma unroll
        for (int ww = 0; ww < 8; ww++) s += red[ww];
        atomicAdd(&g_acc, s);
    }
}

__global__ void k_final(float* out) {
    out[0] = (float)(g_acc * (1.0 / (2.0 * Tt * Bb)));
}

// ---------------- launch ----------------
extern "C" void kernel_launch(void* const* d_in, const int* in_sizes, int n_in,
                              void* d_out, int out_size)
{
    const float* A = (const float*)d_in[0];
    const float* V = (const float*)d_in[1];
    const float* E = (const float*)d_in[2];
    float* out = (float*)d_out;

    static bool inited = false;
    if (!inited) {
        inited = true;
        cudaFuncSetAttribute(k_hmma_sd,    cudaFuncAttributeMaxDynamicSharedMemorySize, DSM);
        cudaFuncSetAttribute(k_hmma_scode, cudaFuncAttributeMaxDynamicSharedMemorySize, DSM);
    }

    k_init<<<1, 1>>>();
    k_cvt<<<2 * Nn + Mm, 128>>>(A, V, E);

    dim3 g1(Mm / 128, Nn / 128, 2);
    k_hmma_sd<<<g1, 256, DSM>>>();

    k_softmax<<<(2 * Nn) / 8, 256>>>();

    dim3 g2(Bb / 128, Bb / 128, 2 * Tt);
    k_hmma_scode<<<g2, 256, DSM>>>();

    k_loss<<<(2 * Tt * Bb) / 256, 256>>>();
    k_final<<<1, 1>>>(out);
}